// round 2
// baseline (speedup 1.0000x reference)
#include <cuda_runtime.h>
#include <math.h>

#define PI_F 3.14159265358979323846f

__device__ __forceinline__ float2 cmul(float2 a, float2 b) {
    return make_float2(a.x*b.x - a.y*b.y, a.x*b.y + a.y*b.x);
}
__device__ __forceinline__ float2 cadd(float2 a, float2 b) {
    return make_float2(a.x + b.x, a.y + b.y);
}

// 128 threads, 16 rows per block, grid = B/16 (2048 for B=32768).
// Phase 1: each warp handles 4 rows as 2 pairs. Lane owns k = lane + 32t
// (scalar coalesced loads, MLP=32 per pair); W_enc streamed from smem via
// conflict-free LDS.128. 6-shuffle reduction per row.
// Phase 2: threads 0..15 each simulate one row's 16-dim statevector in regs.
__global__ __launch_bounds__(128)
void qrnn_cell_kernel(const float* __restrict__ inputs,   // (B, 512)
                      const float* __restrict__ prev_h,   // (B, 4)
                      const float* __restrict__ W_enc,    // (516, 4)
                      const float* __restrict__ b_enc,    // (4,)
                      const float* __restrict__ theta,    // (2, 4, 3)
                      const float* __restrict__ W_out,    // (4, 4)
                      const float* __restrict__ b_out,    // (4,)
                      float* __restrict__ out,            // (B, 4)
                      int B)
{
    __shared__ float4 sW[512];        // W_enc rows 0..511 (w[k][0..3] as float4)
    __shared__ float2 sU[8][4];       // fused U = RY*RZ*RX per (l,q)
    __shared__ float  sWtail[4][4];   // W_enc rows 512..515 (prev_h part)
    __shared__ float  sWout[16];
    __shared__ float  sbenc[4];
    __shared__ float  sbout[4];
    __shared__ float  sPre[16 * 4];   // reduced dot products per local row

    const int tid  = threadIdx.x;
    const int lane = tid & 31;
    const int wid  = tid >> 5;
    const int rowbase = blockIdx.x * 16;

    // ---- prefetch prev_h for phase 2 early (overlaps with everything) -------
    float4 ph = make_float4(0.f, 0.f, 0.f, 0.f);
    if (tid < 16) {
        int prow = rowbase + tid;
        if (prow >= B) prow = B - 1;
        ph = reinterpret_cast<const float4*>(prev_h)[prow];
    }

    // ---- W_enc -> smem (float4 per k-row), conflict-free fill ---------------
    const float4* w4g = reinterpret_cast<const float4*>(W_enc);
    #pragma unroll
    for (int i = 0; i < 4; i++)
        sW[tid + 128 * i] = w4g[tid + 128 * i];

    // ---- batch-independent setup --------------------------------------------
    if (tid < 8) {
        int l = tid >> 2, q = tid & 3;
        const float* th = theta + (l * 4 + q) * 3;
        float ca, sa, cb, sb, cy, sy;
        sincosf(0.5f * th[0], &sa, &ca);
        sincosf(0.5f * th[1], &sb, &cb);
        sincosf(0.5f * th[2], &sy, &cy);
        float2 RX0 = make_float2(ca, 0.f),  RX1 = make_float2(0.f, -sa);
        float2 RX2 = make_float2(0.f, -sa), RX3 = make_float2(ca, 0.f);
        float2 RZ0 = make_float2(cb, -sb),  RZ3 = make_float2(cb, sb);
        float2 M0 = cmul(RZ0, RX0);
        float2 M1 = cmul(RZ0, RX1);
        float2 M2 = cmul(RZ3, RX2);
        float2 M3 = cmul(RZ3, RX3);
        sU[tid][0] = cadd(make_float2(cy * M0.x, cy * M0.y), make_float2(-sy * M2.x, -sy * M2.y));
        sU[tid][1] = cadd(make_float2(cy * M1.x, cy * M1.y), make_float2(-sy * M3.x, -sy * M3.y));
        sU[tid][2] = cadd(make_float2(sy * M0.x, sy * M0.y), make_float2( cy * M2.x,  cy * M2.y));
        sU[tid][3] = cadd(make_float2(sy * M1.x, sy * M1.y), make_float2( cy * M3.x,  cy * M3.y));
    }
    if (tid >= 8 && tid < 12) {
        int r = tid - 8;
        sbenc[r] = b_enc[r];
        sbout[r] = b_out[r];
        #pragma unroll
        for (int j = 0; j < 4; j++)
            sWtail[r][j] = W_enc[(512 + r) * 4 + j];
    }
    if (tid >= 16 && tid < 32) sWout[tid - 16] = W_out[tid - 16];
    __syncthreads();

    // ---------------- phase 1: dot products, 2 pairs of rows per warp --------
    #pragma unroll
    for (int pair = 0; pair < 2; pair++) {
        int lr0 = wid * 4 + pair * 2;            // local row of the pair
        long r0 = (long)rowbase + lr0;
        if (r0 + 1 >= B) r0 = (B >= 2) ? (long)(B - 2) : 0;   // clamp (safety)
        const float* p0 = inputs + r0 * 512 + lane;

        // front-batched loads: 32 independent scalar LDGs (MLP=32)
        float xa[16], xb[16];
        #pragma unroll
        for (int t = 0; t < 16; t++) xa[t] = p0[32 * t];
        #pragma unroll
        for (int t = 0; t < 16; t++) xb[t] = p0[512 + 32 * t];

        float a0 = 0.f, a1 = 0.f, a2 = 0.f, a3 = 0.f;
        float b0 = 0.f, b1 = 0.f, b2 = 0.f, b3 = 0.f;
        #pragma unroll
        for (int t = 0; t < 16; t++) {
            float4 w = sW[32 * t + lane];        // conflict-free LDS.128
            a0 = fmaf(xa[t], w.x, a0);
            a1 = fmaf(xa[t], w.y, a1);
            a2 = fmaf(xa[t], w.z, a2);
            a3 = fmaf(xa[t], w.w, a3);
            b0 = fmaf(xb[t], w.x, b0);
            b1 = fmaf(xb[t], w.y, b1);
            b2 = fmaf(xb[t], w.z, b2);
            b3 = fmaf(xb[t], w.w, b3);
        }

        // 6-shuffle reduction per row: lane ends with S_{lane&3}
        // row a
        {
            bool p1b = lane & 1, p2b = lane & 2;
            float v01 = p1b ? a1 : a0, o01 = p1b ? a0 : a1;
            v01 += __shfl_xor_sync(0xffffffffu, o01, 1);
            float v23 = p1b ? a3 : a2, o23 = p1b ? a2 : a3;
            v23 += __shfl_xor_sync(0xffffffffu, o23, 1);
            float v = p2b ? v23 : v01, o = p2b ? v01 : v23;
            v += __shfl_xor_sync(0xffffffffu, o, 2);
            v += __shfl_xor_sync(0xffffffffu, v, 4);
            v += __shfl_xor_sync(0xffffffffu, v, 8);
            v += __shfl_xor_sync(0xffffffffu, v, 16);
            a0 = v;
        }
        // row b
        {
            bool p1b = lane & 1, p2b = lane & 2;
            float v01 = p1b ? b1 : b0, o01 = p1b ? b0 : b1;
            v01 += __shfl_xor_sync(0xffffffffu, o01, 1);
            float v23 = p1b ? b3 : b2, o23 = p1b ? b2 : b3;
            v23 += __shfl_xor_sync(0xffffffffu, o23, 1);
            float v = p2b ? v23 : v01, o = p2b ? v01 : v23;
            v += __shfl_xor_sync(0xffffffffu, o, 2);
            v += __shfl_xor_sync(0xffffffffu, v, 4);
            v += __shfl_xor_sync(0xffffffffu, v, 8);
            v += __shfl_xor_sync(0xffffffffu, v, 16);
            b0 = v;
        }
        if (lane < 4)       sPre[lr0 * 4 + lane] = a0;
        else if (lane < 8)  sPre[(lr0 + 1) * 4 + (lane & 3)] = b0;
    }
    __syncthreads();

    // ---------------- phase 2: per-row quantum circuit in registers ----------
    if (tid < 16) {
        int row = rowbase + tid;
        if (row < B) {
            float acc[4];
            #pragma unroll
            for (int j = 0; j < 4; j++) {
                acc[j] = sPre[tid * 4 + j] + sbenc[j]
                       + ph.x * sWtail[0][j] + ph.y * sWtail[1][j]
                       + ph.z * sWtail[2][j] + ph.w * sWtail[3][j];
            }
            // half-angles of RY encodings: tanh(.)*pi*0.5 in [-pi/2, pi/2]
            float cv[4], sv[4];
            #pragma unroll
            for (int q = 0; q < 4; q++) {
                float half = tanhf(acc[q]) * (0.5f * PI_F);
                __sincosf(half, &sv[q], &cv[q]);
            }
            // product state (real)
            float sr[16], si[16];
            #pragma unroll
            for (int i = 0; i < 16; i++) {
                float v = ((i & 8) ? sv[0] : cv[0])
                        * ((i & 4) ? sv[1] : cv[1])
                        * ((i & 2) ? sv[2] : cv[2])
                        * ((i & 1) ? sv[3] : cv[3]);
                sr[i] = v;
                si[i] = 0.f;
            }
            // L=2 layers: fused 1q gate per qubit, then CNOT chain
            #pragma unroll
            for (int l = 0; l < 2; l++) {
                #pragma unroll
                for (int q = 0; q < 4; q++) {
                    float2 u00 = sU[l*4+q][0];
                    float2 u01 = sU[l*4+q][1];
                    float2 u10 = sU[l*4+q][2];
                    float2 u11 = sU[l*4+q][3];
                    const int m = 8 >> q;
                    #pragma unroll
                    for (int i = 0; i < 16; i++) {
                        if (i & m) continue;
                        const int i1 = i | m;
                        float ar = sr[i],  ai = si[i];
                        float br = sr[i1], bi = si[i1];
                        sr[i]  = u00.x*ar - u00.y*ai + u01.x*br - u01.y*bi;
                        si[i]  = u00.x*ai + u00.y*ar + u01.x*bi + u01.y*br;
                        sr[i1] = u10.x*ar - u10.y*ai + u11.x*br - u11.y*bi;
                        si[i1] = u10.x*ai + u10.y*ar + u11.x*bi + u11.y*br;
                    }
                }
                #pragma unroll
                for (int q = 0; q < 3; q++) {
                    const int mc = 8 >> q, mt = 4 >> q;
                    #pragma unroll
                    for (int i = 0; i < 16; i++) {
                        if ((i & mc) && !(i & mt)) {
                            const int i1 = i | mt;
                            float tr = sr[i]; sr[i] = sr[i1]; sr[i1] = tr;
                            float ti = si[i]; si[i] = si[i1]; si[i1] = ti;
                        }
                    }
                }
            }
            // PauliZ expectations
            float ev[4] = {0.f, 0.f, 0.f, 0.f};
            #pragma unroll
            for (int i = 0; i < 16; i++) {
                float p = sr[i]*sr[i] + si[i]*si[i];
                ev[0] += (i & 8) ? -p : p;
                ev[1] += (i & 4) ? -p : p;
                ev[2] += (i & 2) ? -p : p;
                ev[3] += (i & 1) ? -p : p;
            }
            // next_h = tanh(ev @ W_out + b_out)
            float4 o;
            o.x = tanhf(ev[0]*sWout[0] + ev[1]*sWout[4] + ev[2]*sWout[8]  + ev[3]*sWout[12] + sbout[0]);
            o.y = tanhf(ev[0]*sWout[1] + ev[1]*sWout[5] + ev[2]*sWout[9]  + ev[3]*sWout[13] + sbout[1]);
            o.z = tanhf(ev[0]*sWout[2] + ev[1]*sWout[6] + ev[2]*sWout[10] + ev[3]*sWout[14] + sbout[2]);
            o.w = tanhf(ev[0]*sWout[3] + ev[1]*sWout[7] + ev[2]*sWout[11] + ev[3]*sWout[15] + sbout[3]);
            reinterpret_cast<float4*>(out)[row] = o;
        }
    }
}

extern "C" void kernel_launch(void* const* d_in, const int* in_sizes, int n_in,
                              void* d_out, int out_size)
{
    const float* inputs = (const float*)d_in[0];
    const float* prev_h = (const float*)d_in[1];
    const float* W_enc  = (const float*)d_in[2];
    const float* b_enc  = (const float*)d_in[3];
    const float* theta  = (const float*)d_in[4];
    const float* W_out  = (const float*)d_in[5];
    const float* b_out  = (const float*)d_in[6];

    int B = in_sizes[0] / 512;
    int grid = (B + 15) / 16;
    qrnn_cell_kernel<<<grid, 128>>>(inputs, prev_h, W_enc, b_enc, theta,
                                    W_out, b_out, (float*)d_out, B);
}